// round 10
// baseline (speedup 1.0000x reference)
#include <cuda_runtime.h>
#include <cuda_fp16.h>
#include <math.h>
#include <cstdint>

#define NB 8
#define COUT 64
#define HOUT 63

// ---- scratch (device globals, zero-initialized; no cudaMalloc) ----
// XA2: [b][ks 6][m 1072][qc 4] -> uint4 = (hA, hB, lA, lB); kpA=ks*8+qc, kpB=kpA+4
__device__ __align__(16) uint4 g_XA2[NB * 6 * 1072 * 4];
// WB2: [pl 9][jn 8][ks 6][lane 32] -> uint2 = (b0, b1) fragment regs (hi only)
__device__ __align__(16) uint2 g_WB2[9 * 8 * 6 * 32];

// classes: 0=oo(4 planes) 1=oe(2) 2=eo(2) 3=ee(1); plane id = kh*3+kw
__constant__ int c_dlt[4][4] = {{33,32,1,0},{32,0,0,0},{1,0,0,0},{0,0,0,0}};
__constant__ int c_pl[4][4]  = {{0,2,6,8},{1,7,0,0},{3,5,0,0},{4,0,0,0}};
__constant__ int c_oh[4] = {1, 1, 0, 0};
__constant__ int c_ow[4] = {1, 0, 1, 0};

__device__ __forceinline__ uint32_t pack_h2(float f0, float f1) {
    __half h0 = __float2half_rn(f0);
    __half h1 = __float2half_rn(f1);
    return (uint32_t)__half_as_ushort(h0) | ((uint32_t)__half_as_ushort(h1) << 16);
}

// ================= prep (+wc) single launch =================
__global__ void __launch_bounds__(128)
prep_kernel(const float* __restrict__ x, const float* __restrict__ w) {
    if (blockIdx.x < 512) {
        __shared__ float sm[3][32][17];
        const int b    = blockIdx.x >> 6;
        const int mb16 = blockIdx.x & 63;
        const int tid  = threadIdx.x;
        const int ci = tid >> 2;
        const int mg = tid & 3;

        const float4* p = (const float4*)x + ((size_t)(b * 32 + ci) * 16) * 256 + mb16 * 4 + mg;
        float4 v = p[0];
        float4 s = v, d0 = v, d15 = v;
#pragma unroll
        for (int d = 1; d < 16; d++) {
            float4 u = p[d * 256];
            s.x += u.x; s.y += u.y; s.z += u.z; s.w += u.w;
            if (d == 15) d15 = u;
        }
        const int mo = mg * 4;
        sm[0][ci][mo + 0] = s.x;   sm[0][ci][mo + 1] = s.y;
        sm[0][ci][mo + 2] = s.z;   sm[0][ci][mo + 3] = s.w;
        sm[1][ci][mo + 0] = d0.x;  sm[1][ci][mo + 1] = d0.y;
        sm[1][ci][mo + 2] = d0.z;  sm[1][ci][mo + 3] = d0.w;
        sm[2][ci][mo + 0] = d15.x; sm[2][ci][mo + 1] = d15.y;
        sm[2][ci][mo + 2] = d15.z; sm[2][ci][mo + 3] = d15.w;
        __syncthreads();

#pragma unroll
        for (int it = 0; it < 3; it++) {
            int i = tid + it * 128;
            int qc  = i & 3;
            int ks  = (i >> 2) % 6;
            int row = i / 24;
            int kpA = ks * 8 + qc;
            int kpB = kpA + 4;
            int spA = kpA >> 4, cA = (2 * kpA) & 31;
            int spB = kpB >> 4, cB = (2 * kpB) & 31;
            float fA0 = sm[spA][cA][row],     fA1 = sm[spA][cA + 1][row];
            float fB0 = sm[spB][cB][row],     fB1 = sm[spB][cB + 1][row];
            __half hA0 = __float2half_rn(fA0), hA1 = __float2half_rn(fA1);
            __half hB0 = __float2half_rn(fB0), hB1 = __float2half_rn(fB1);
            uint32_t hA = (uint32_t)__half_as_ushort(hA0) | ((uint32_t)__half_as_ushort(hA1) << 16);
            uint32_t hB = (uint32_t)__half_as_ushort(hB0) | ((uint32_t)__half_as_ushort(hB1) << 16);
            uint32_t lA = pack_h2(fA0 - __half2float(hA0), fA1 - __half2float(hA1));
            uint32_t lB = pack_h2(fB0 - __half2float(hB0), fB1 - __half2float(hB1));
            size_t idx = (((size_t)b * 6 + ks) * 1072 + mb16 * 16 + row) * 4 + qc;
            g_XA2[idx] = make_uint4(hA, hB, lA, lB);
        }
    } else {
        int i = (blockIdx.x - 512) * 128 + threadIdx.x;   // 0 .. 9*8*6*32-1
        if (i >= 9 * 8 * 6 * 32) return;
        int lane = i & 31;
        int ks   = (i >> 5) % 6;
        int jn   = (i / 192) & 7;
        int pl   = i / 1536;
        int qr = lane >> 2, qc = lane & 3;
        int n  = jn * 8 + qr;
        int kh = pl / 3, kw = pl % 3;
        float f[4];
#pragma unroll
        for (int j = 0; j < 4; j++) {
            int kp  = ks * 8 + qc + (j >> 1) * 4;
            int c96 = 2 * kp + (j & 1);
            int sidx = c96 >> 5, ci = c96 & 31;
            int base = (ci * 64 + n) * 27 + kh * 3 + kw;
            float v;
            if (sidx == 0)      v = w[base] + w[base + 9] + w[base + 18];
            else if (sidx == 1) v = -w[base];
            else                v = -w[base + 18];
            f[j] = v;
        }
        g_WB2[i] = make_uint2(pack_h2(f[0], f[1]), pack_h2(f[2], f[3]));
    }
}

// ================= HMMA GEMM (balanced blocks) + fused epilogue =================
__device__ __forceinline__ void mma16816(float* d,
                                         uint32_t a0, uint32_t a1, uint32_t a2, uint32_t a3,
                                         uint32_t b0, uint32_t b1) {
    asm volatile(
        "mma.sync.aligned.m16n8k16.row.col.f32.f16.f16.f32 "
        "{%0,%1,%2,%3},{%4,%5,%6,%7},{%8,%9},{%0,%1,%2,%3};"
        : "+f"(d[0]), "+f"(d[1]), "+f"(d[2]), "+f"(d[3])
        : "r"(a0), "r"(a1), "r"(a2), "r"(a3), "r"(b0), "r"(b1));
}

// grid 640. cls0: bid<256, mt of 32 m, 2 m-warps x 4 k-groups (1 plane/group).
// cls1: [256,384), cls2: [384,512): mt 64, 4m x 2k (1 plane/group).
// cls3: [512,640): mt 64, 4m x 2k (half-plane/group: 3 ksteps).
__global__ void __launch_bounds__(256, 3)
mma_fused(const float* __restrict__ conv_bias,
          const float* __restrict__ bias,
          float* __restrict__ out) {
    __shared__ float scb[COUT];
    __shared__ float red[6][32][32];     // 24KB: grp>0 warps (max 6)

    const int tid  = threadIdx.x;
    const int w    = tid >> 5;
    const int lane = tid & 31;
    if (tid < COUT) scb[tid] = conv_bias[tid] + bias[tid];

    const int bid = blockIdx.x;
    int cls, b, mt, lgNMW, NKG, mtile;
    if (bid < 256)      { cls = 0; b = bid >> 5;          mt = bid & 31;          lgNMW = 1; NKG = 4; mtile = 32; }
    else if (bid < 384) { cls = 1; b = (bid - 256) >> 4;  mt = (bid - 256) & 15;  lgNMW = 2; NKG = 2; mtile = 64; }
    else if (bid < 512) { cls = 2; b = (bid - 384) >> 4;  mt = (bid - 384) & 15;  lgNMW = 2; NKG = 2; mtile = 64; }
    else                { cls = 3; b = (bid - 512) >> 4;  mt = (bid - 512) & 15;  lgNMW = 2; NKG = 2; mtile = 64; }
    const int NMW = 1 << lgNMW;
    const int wm  = w & (NMW - 1);
    const int grp = w >> lgNMW;
    const int mw  = mt * mtile + wm * 16;
    const int qr = lane >> 2;
    const int qc = lane & 3;

    // group -> (plane, ks range)
    const int pli = (cls == 3) ? 0 : grp;
    const int ks0 = (cls == 3) ? grp * 3 : 0;
    const int ksn = (cls == 3) ? 3 : 6;
    const int dlt = c_dlt[cls][pli];
    const int pl  = c_pl[cls][pli];

    float acc[8][4];
#pragma unroll
    for (int j = 0; j < 8; j++)
#pragma unroll
        for (int t = 0; t < 4; t++) acc[j][t] = 0.f;

    const uint4* __restrict__ A0 =
        g_XA2 + (((size_t)b * 6 + ks0) * 1072 + mw + dlt + qr) * 4 + qc;
    const uint2* __restrict__ B0 =
        g_WB2 + ((size_t)pl * 48 + ks0) * 32 + lane;

    uint4 av0 = A0[0];
    uint4 av1 = A0[32];
#pragma unroll 3
    for (int ks = 0; ks < ksn; ks++) {
        uint4 nv0, nv1;
        if (ks + 1 < ksn) {
            A0 += 1072 * 4;
            nv0 = A0[0];
            nv1 = A0[32];
        }
#pragma unroll
        for (int jn = 0; jn < 8; jn++) {
            uint2 bv = B0[jn * 192];
            mma16816(acc[jn], av0.x, av1.x, av0.y, av1.y, bv.x, bv.y);  // hi
            mma16816(acc[jn], av0.z, av1.z, av0.w, av1.w, bv.x, bv.y);  // lo
        }
        B0 += 32;
        av0 = nv0; av1 = nv1;
    }

    // ---- cross-group reduction (grp>0 warps park partials, grp0 sums) ----
    if (grp > 0) {
        const int ri = w - NMW;
#pragma unroll
        for (int jn = 0; jn < 8; jn += 2) {
            *(float4*)&red[ri][lane][jn * 4]     = *(float4*)&acc[jn][0];
            *(float4*)&red[ri][lane][jn * 4 + 4] = *(float4*)&acc[jn + 1][0];
        }
    }
    __syncthreads();
    if (grp > 0) return;

    for (int g = 1; g < NKG; g++) {
        const int ri = (g - 1) * NMW + wm;
#pragma unroll
        for (int jn = 0; jn < 8; jn++) {
#pragma unroll
            for (int t = 0; t < 4; t++) acc[jn][t] += red[ri][lane][jn * 4 + t];
        }
    }

    // ---- fused epilogue: mean-scale + biases + softmax + 2*tanh ----
    const float inv_d = 1.0f / 31.0f;
    float mx0 = -INFINITY, mx1 = -INFINITY;
#pragma unroll
    for (int jn = 0; jn < 8; jn++) {
#pragma unroll
        for (int t = 0; t < 2; t++) {
            float c = scb[jn * 8 + 2 * qc + t];
            acc[jn][t]     = acc[jn][t]     * inv_d + c;
            acc[jn][2 + t] = acc[jn][2 + t] * inv_d + c;
            mx0 = fmaxf(mx0, acc[jn][t]);
            mx1 = fmaxf(mx1, acc[jn][2 + t]);
        }
    }
    mx0 = fmaxf(mx0, __shfl_xor_sync(0xffffffffu, mx0, 1));
    mx0 = fmaxf(mx0, __shfl_xor_sync(0xffffffffu, mx0, 2));
    mx1 = fmaxf(mx1, __shfl_xor_sync(0xffffffffu, mx1, 1));
    mx1 = fmaxf(mx1, __shfl_xor_sync(0xffffffffu, mx1, 2));

    float s0 = 0.f, s1 = 0.f;
#pragma unroll
    for (int jn = 0; jn < 8; jn++) {
#pragma unroll
        for (int t = 0; t < 2; t++) {
            acc[jn][t]     = __expf(acc[jn][t] - mx0);
            acc[jn][2 + t] = __expf(acc[jn][2 + t] - mx1);
            s0 += acc[jn][t];
            s1 += acc[jn][2 + t];
        }
    }
    s0 += __shfl_xor_sync(0xffffffffu, s0, 1);
    s0 += __shfl_xor_sync(0xffffffffu, s0, 2);
    s1 += __shfl_xor_sync(0xffffffffu, s1, 1);
    s1 += __shfl_xor_sync(0xffffffffu, s1, 2);
    const float rs0 = 1.0f / s0;
    const float rs1 = 1.0f / s1;

    const int oh = c_oh[cls], ow = c_ow[cls];
    const int m0 = mw + qr;
    const int hq = m0 >> 5;
    const int wq0 = m0 & 31;
    const int ho = 2 * hq + oh;
    const int wo0 = 2 * wq0 + ow;
    const int wo1 = 2 * (wq0 + 8) + ow;
    float* obase = out + (size_t)b * COUT * (HOUT * HOUT) + (size_t)ho * HOUT;

    if (ho < HOUT) {
        const bool v0 = (wo0 < HOUT);
        const bool v1 = (wo1 < HOUT);
#pragma unroll
        for (int jn = 0; jn < 8; jn++) {
#pragma unroll
            for (int t = 0; t < 2; t++) {
                int ch = jn * 8 + 2 * qc + t;
                float* op = obase + (size_t)ch * (HOUT * HOUT);
                if (v0) {
                    float s = acc[jn][t] * rs0;
                    op[wo0] = __fdividef(4.0f, 1.0f + __expf(-2.0f * s)) - 2.0f;  // 2*tanh
                }
                if (v1) {
                    float s = acc[jn][2 + t] * rs1;
                    op[wo1] = __fdividef(4.0f, 1.0f + __expf(-2.0f * s)) - 2.0f;
                }
            }
        }
    }
}

extern "C" void kernel_launch(void* const* d_in, const int* in_sizes, int n_in,
                              void* d_out, int out_size) {
    (void)in_sizes; (void)n_in; (void)out_size;
    const float* x         = (const float*)d_in[0];
    const float* w         = (const float*)d_in[1];
    const float* conv_bias = (const float*)d_in[2];
    const float* bias      = (const float*)d_in[3];
    float* out             = (float*)d_out;

    prep_kernel<<<620, 128>>>(x, w);
    mma_fused<<<640, 256>>>(conv_bias, bias, out);
}

// round 11
// speedup vs baseline: 1.0805x; 1.0805x over previous
#include <cuda_runtime.h>
#include <cuda_fp16.h>
#include <math.h>
#include <cstdint>

#define NB 8
#define COUT 64
#define HOUT 63

// ---- scratch (device globals, zero-initialized; no cudaMalloc) ----
// XA2: [b][ks 6][m 1072][qc 4] -> uint2 = (hA, hB) fp16x2; kpA=ks*8+qc, kpB=kpA+4
__device__ __align__(16) uint2 g_XA2[NB * 6 * 1072 * 4];
// WB2: [pl 9][jn 8][ks 6][lane 32] -> uint2 = (b0, b1) fragment regs
__device__ __align__(16) uint2 g_WB2[9 * 8 * 6 * 32];

// classes (heavy first): 0=oo(4 planes) 1=oe(2) 2=eo(2) 3=ee(1)
__constant__ int c_dlt[4][4] = {{33,32,1,0},{32,0,0,0},{1,0,0,0},{0,0,0,0}};
__constant__ int c_pl[4][4]  = {{0,2,6,8},{1,7,0,0},{3,5,0,0},{4,0,0,0}};  // plane id kh*3+kw
__constant__ int c_np[4] = {4, 2, 2, 1};
__constant__ int c_oh[4] = {1, 1, 0, 0};
__constant__ int c_ow[4] = {1, 0, 1, 0};

__device__ __forceinline__ uint32_t pack_h2(float f0, float f1) {
    __half h0 = __float2half_rn(f0);
    __half h1 = __float2half_rn(f1);
    return (uint32_t)__half_as_ushort(h0) | ((uint32_t)__half_as_ushort(h1) << 16);
}

// ================= prep (+wc) single launch =================
// blocks [0,512): prep x. blocks [512, 512+108): wc weights.
__global__ void __launch_bounds__(128)
prep_kernel(const float* __restrict__ x, const float* __restrict__ w) {
    if (blockIdx.x < 512) {
        __shared__ float sm[3][32][17];
        const int b    = blockIdx.x >> 6;
        const int mb16 = blockIdx.x & 63;       // 16-m tile
        const int tid  = threadIdx.x;
        const int ci = tid >> 2;
        const int mg = tid & 3;

        const float4* p = (const float4*)x + ((size_t)(b * 32 + ci) * 16) * 256 + mb16 * 4 + mg;
        float4 v = p[0];
        float4 s = v, d0 = v, d15 = v;
#pragma unroll
        for (int d = 1; d < 16; d++) {
            float4 u = p[d * 256];
            s.x += u.x; s.y += u.y; s.z += u.z; s.w += u.w;
            if (d == 15) d15 = u;
        }
        const int mo = mg * 4;
        sm[0][ci][mo + 0] = s.x;   sm[0][ci][mo + 1] = s.y;
        sm[0][ci][mo + 2] = s.z;   sm[0][ci][mo + 3] = s.w;
        sm[1][ci][mo + 0] = d0.x;  sm[1][ci][mo + 1] = d0.y;
        sm[1][ci][mo + 2] = d0.z;  sm[1][ci][mo + 3] = d0.w;
        sm[2][ci][mo + 0] = d15.x; sm[2][ci][mo + 1] = d15.y;
        sm[2][ci][mo + 2] = d15.z; sm[2][ci][mo + 3] = d15.w;
        __syncthreads();

#pragma unroll
        for (int it = 0; it < 3; it++) {
            int i = tid + it * 128;             // 0 .. 16*6*4-1
            int qc  = i & 3;
            int ks  = (i >> 2) % 6;
            int row = i / 24;
            int kpA = ks * 8 + qc;
            int kpB = kpA + 4;
            int spA = kpA >> 4, cA = (2 * kpA) & 31;
            int spB = kpB >> 4, cB = (2 * kpB) & 31;
            uint32_t hA = pack_h2(sm[spA][cA][row], sm[spA][cA + 1][row]);
            uint32_t hB = pack_h2(sm[spB][cB][row], sm[spB][cB + 1][row]);
            size_t idx = (((size_t)b * 6 + ks) * 1072 + mb16 * 16 + row) * 4 + qc;
            g_XA2[idx] = make_uint2(hA, hB);
        }
    } else {
        // wc -> fragment layout [pl][jn][ks][lane]
        int i = (blockIdx.x - 512) * 128 + threadIdx.x;   // 0 .. 9*8*6*32-1
        if (i >= 9 * 8 * 6 * 32) return;
        int lane = i & 31;
        int ks   = (i >> 5) % 6;
        int jn   = (i / 192) & 7;
        int pl   = i / 1536;
        int qr = lane >> 2, qc = lane & 3;
        int n  = jn * 8 + qr;
        int kh = pl / 3, kw = pl % 3;
        float f[4];
#pragma unroll
        for (int j = 0; j < 4; j++) {
            int kp  = ks * 8 + qc + (j >> 1) * 4;      // kpA, kpA, kpB, kpB
            int c96 = 2 * kp + (j & 1);
            int sidx = c96 >> 5, ci = c96 & 31;
            int base = (ci * 64 + n) * 27 + kh * 3 + kw;
            float v;
            if (sidx == 0)      v = w[base] + w[base + 9] + w[base + 18];
            else if (sidx == 1) v = -w[base];
            else                v = -w[base + 18];
            f[j] = v;
        }
        g_WB2[i] = make_uint2(pack_h2(f[0], f[1]), pack_h2(f[2], f[3]));
    }
}

// ================= HMMA GEMM (2-way k-split) + fused epilogue =================
__device__ __forceinline__ void mma16816(float* d,
                                         uint32_t a0, uint32_t a1, uint32_t a2, uint32_t a3,
                                         uint32_t b0, uint32_t b1) {
    asm volatile(
        "mma.sync.aligned.m16n8k16.row.col.f32.f16.f16.f32 "
        "{%0,%1,%2,%3},{%4,%5,%6,%7},{%8,%9},{%0,%1,%2,%3};"
        : "+f"(d[0]), "+f"(d[1]), "+f"(d[2]), "+f"(d[3])
        : "r"(a0), "r"(a1), "r"(a2), "r"(a3), "r"(b0), "r"(b1));
}

// grid 512: cls=bid>>7 (heavy first), b=(bid>>4)&7, mt=bid&15. Block 64m x 64n.
// 8 warps: grp=w>>2 splits ksteps; warp handles m rows [mt*64 + (w&3)*16, +16).
__global__ void __launch_bounds__(256, 4)
mma_fused(const float* __restrict__ conv_bias,
          const float* __restrict__ bias,
          float* __restrict__ out) {
    __shared__ float scb[COUT];
    __shared__ float red[4][32][32];     // 16KB reduction buffer

    const int tid  = threadIdx.x;
    const int w    = tid >> 5;
    const int lane = tid & 31;
    const int wm   = w & 3;
    const int grp  = w >> 2;
    if (tid < COUT) scb[tid] = conv_bias[tid] + bias[tid];

    const int bid = blockIdx.x;
    const int cls = bid >> 7;
    const int b   = (bid >> 4) & 7;
    const int mt  = bid & 15;
    const int mw  = mt * 64 + wm * 16;
    const int qr = lane >> 2;
    const int qc = lane & 3;

    float acc[8][4];
#pragma unroll
    for (int j = 0; j < 8; j++)
#pragma unroll
        for (int t = 0; t < 4; t++) acc[j][t] = 0.f;

    const int halfT = c_np[cls] * 3;
    const int sb = grp * halfT;
    for (int s = sb; s < sb + halfT; s++) {
        const int pli = s / 6;                    // class-local plane index
        const int ks  = s - pli * 6;
        const int dlt = c_dlt[cls][pli];
        const int pl  = c_pl[cls][pli];

        const uint2* __restrict__ A0 =
            g_XA2 + (((size_t)b * 6 + ks) * 1072 + mw + dlt + qr) * 4 + qc;
        const uint2* __restrict__ B0 =
            g_WB2 + ((size_t)pl * 8 * 6 + ks) * 32 + lane;

        uint2 av0 = A0[0];        // row qr:   (hA, hB)
        uint2 av1 = A0[8 * 4];    // row qr+8
#pragma unroll
        for (int jn = 0; jn < 8; jn++) {
            uint2 bv = B0[jn * 192];
            mma16816(acc[jn], av0.x, av1.x, av0.y, av1.y, bv.x, bv.y);
        }
    }

    // ---- cross-group reduction ----
    if (grp == 1) {
#pragma unroll
        for (int jn = 0; jn < 8; jn += 2) {
            *(float4*)&red[wm][lane][jn * 4]     = *(float4*)&acc[jn][0];
            *(float4*)&red[wm][lane][jn * 4 + 4] = *(float4*)&acc[jn + 1][0];
        }
    }
    __syncthreads();
    if (grp == 1) return;

#pragma unroll
    for (int jn = 0; jn < 8; jn++) {
#pragma unroll
        for (int t = 0; t < 4; t++) acc[jn][t] += red[wm][lane][jn * 4 + t];
    }

    // ---- fused epilogue: mean-scale + biases + softmax + 2*tanh ----
    const float inv_d = 1.0f / 31.0f;
    float mx0 = -INFINITY, mx1 = -INFINITY;
#pragma unroll
    for (int jn = 0; jn < 8; jn++) {
#pragma unroll
        for (int t = 0; t < 2; t++) {
            float c = scb[jn * 8 + 2 * qc + t];
            acc[jn][t]     = acc[jn][t]     * inv_d + c;
            acc[jn][2 + t] = acc[jn][2 + t] * inv_d + c;
            mx0 = fmaxf(mx0, acc[jn][t]);
            mx1 = fmaxf(mx1, acc[jn][2 + t]);
        }
    }
    mx0 = fmaxf(mx0, __shfl_xor_sync(0xffffffffu, mx0, 1));
    mx0 = fmaxf(mx0, __shfl_xor_sync(0xffffffffu, mx0, 2));
    mx1 = fmaxf(mx1, __shfl_xor_sync(0xffffffffu, mx1, 1));
    mx1 = fmaxf(mx1, __shfl_xor_sync(0xffffffffu, mx1, 2));

    float s0 = 0.f, s1 = 0.f;
#pragma unroll
    for (int jn = 0; jn < 8; jn++) {
#pragma unroll
        for (int t = 0; t < 2; t++) {
            acc[jn][t]     = __expf(acc[jn][t] - mx0);
            acc[jn][2 + t] = __expf(acc[jn][2 + t] - mx1);
            s0 += acc[jn][t];
            s1 += acc[jn][2 + t];
        }
    }
    s0 += __shfl_xor_sync(0xffffffffu, s0, 1);
    s0 += __shfl_xor_sync(0xffffffffu, s0, 2);
    s1 += __shfl_xor_sync(0xffffffffu, s1, 1);
    s1 += __shfl_xor_sync(0xffffffffu, s1, 2);
    const float rs0 = 1.0f / s0;
    const float rs1 = 1.0f / s1;

    const int oh = c_oh[cls], ow = c_ow[cls];
    const int m0 = mw + qr;
    const int hq = m0 >> 5;
    const int wq0 = m0 & 31;
    const int ho = 2 * hq + oh;
    const int wo0 = 2 * wq0 + ow;
    const int wo1 = 2 * (wq0 + 8) + ow;
    float* obase = out + (size_t)b * COUT * (HOUT * HOUT) + (size_t)ho * HOUT;

    if (ho < HOUT) {
        const bool v0 = (wo0 < HOUT);
        const bool v1 = (wo1 < HOUT);
#pragma unroll
        for (int jn = 0; jn < 8; jn++) {
#pragma unroll
            for (int t = 0; t < 2; t++) {
                int ch = jn * 8 + 2 * qc + t;
                float* op = obase + (size_t)ch * (HOUT * HOUT);
                if (v0) {
                    float s = acc[jn][t] * rs0;
                    op[wo0] = __fdividef(4.0f, 1.0f + __expf(-2.0f * s)) - 2.0f;  // 2*tanh
                }
                if (v1) {
                    float s = acc[jn][2 + t] * rs1;
                    op[wo1] = __fdividef(4.0f, 1.0f + __expf(-2.0f * s)) - 2.0f;
                }
            }
        }
    }
}

extern "C" void kernel_launch(void* const* d_in, const int* in_sizes, int n_in,
                              void* d_out, int out_size) {
    (void)in_sizes; (void)n_in; (void)out_size;
    const float* x         = (const float*)d_in[0];
    const float* w         = (const float*)d_in[1];
    const float* conv_bias = (const float*)d_in[2];
    const float* bias      = (const float*)d_in[3];
    float* out             = (float*)d_out;

    prep_kernel<<<620, 128>>>(x, w);
    mma_fused<<<512, 256>>>(conv_bias, bias, out);
}

// round 12
// speedup vs baseline: 1.2877x; 1.1918x over previous
#include <cuda_runtime.h>
#include <cuda_fp16.h>
#include <math.h>
#include <cstdint>

#define NB 8
#define COUT 64
#define HOUT 63

// ---- scratch (device globals, zero-initialized; no cudaMalloc) ----
// XA2: [b][ks 6][m 1072][qc 4] -> uint2 = (hA, hB) fp16x2; kpA=ks*8+qc, kpB=kpA+4
__device__ __align__(16) uint2 g_XA2[NB * 6 * 1072 * 4];
// WB4: [pl 9][ks 6][jnp 4][lane 32] -> uint4 = (b0_e, b1_e, b0_o, b1_o) for jn=2*jnp{,+1}
__device__ __align__(16) uint4 g_WB4[9 * 6 * 4 * 32];

// classes (heavy first): 0=oo(4 planes) 1=oe(2) 2=eo(2) 3=ee(1)
__constant__ int c_dlt[4][4] = {{33,32,1,0},{32,0,0,0},{1,0,0,0},{0,0,0,0}};
__constant__ int c_pl[4][4]  = {{0,2,6,8},{1,7,0,0},{3,5,0,0},{4,0,0,0}};  // plane id kh*3+kw
__constant__ int c_np[4] = {4, 2, 2, 1};
__constant__ int c_oh[4] = {1, 1, 0, 0};
__constant__ int c_ow[4] = {1, 0, 1, 0};

__device__ __forceinline__ uint32_t pack_h2(float f0, float f1) {
    __half h0 = __float2half_rn(f0);
    __half h1 = __float2half_rn(f1);
    return (uint32_t)__half_as_ushort(h0) | ((uint32_t)__half_as_ushort(h1) << 16);
}

// ================= prep (+wc) single launch =================
// blocks [0,512): prep x. blocks [512, 512+54): wc weights.
__global__ void __launch_bounds__(128)
prep_kernel(const float* __restrict__ x, const float* __restrict__ w) {
    if (blockIdx.x < 512) {
        __shared__ float sm[3][32][17];
        const int b    = blockIdx.x >> 6;
        const int mb16 = blockIdx.x & 63;       // 16-m tile
        const int tid  = threadIdx.x;
        const int ci = tid >> 2;
        const int mg = tid & 3;

        const float4* p = (const float4*)x + ((size_t)(b * 32 + ci) * 16) * 256 + mb16 * 4 + mg;
        float4 v = p[0];
        float4 s = v, d0 = v, d15 = v;
#pragma unroll
        for (int d = 1; d < 16; d++) {
            float4 u = p[d * 256];
            s.x += u.x; s.y += u.y; s.z += u.z; s.w += u.w;
            if (d == 15) d15 = u;
        }
        const int mo = mg * 4;
        sm[0][ci][mo + 0] = s.x;   sm[0][ci][mo + 1] = s.y;
        sm[0][ci][mo + 2] = s.z;   sm[0][ci][mo + 3] = s.w;
        sm[1][ci][mo + 0] = d0.x;  sm[1][ci][mo + 1] = d0.y;
        sm[1][ci][mo + 2] = d0.z;  sm[1][ci][mo + 3] = d0.w;
        sm[2][ci][mo + 0] = d15.x; sm[2][ci][mo + 1] = d15.y;
        sm[2][ci][mo + 2] = d15.z; sm[2][ci][mo + 3] = d15.w;
        __syncthreads();

#pragma unroll
        for (int it = 0; it < 3; it++) {
            int i = tid + it * 128;             // 0 .. 16*6*4-1
            int qc  = i & 3;
            int ks  = (i >> 2) % 6;
            int row = i / 24;
            int kpA = ks * 8 + qc;
            int kpB = kpA + 4;
            int spA = kpA >> 4, cA = (2 * kpA) & 31;
            int spB = kpB >> 4, cB = (2 * kpB) & 31;
            uint32_t hA = pack_h2(sm[spA][cA][row], sm[spA][cA + 1][row]);
            uint32_t hB = pack_h2(sm[spB][cB][row], sm[spB][cB + 1][row]);
            size_t idx = (((size_t)b * 6 + ks) * 1072 + mb16 * 16 + row) * 4 + qc;
            g_XA2[idx] = make_uint2(hA, hB);
        }
    } else {
        // wc -> fragment layout [pl][ks][jnp][lane], two jn per uint4
        int i = (blockIdx.x - 512) * 128 + threadIdx.x;   // 0 .. 9*6*4*32-1
        if (i >= 9 * 6 * 4 * 32) return;
        int lane = i & 31;
        int jnp  = (i >> 5) & 3;
        int ks   = (i / 128) % 6;
        int pl   = i / 768;
        int qr = lane >> 2, qc = lane & 3;
        int kh = pl / 3, kw = pl % 3;
        uint32_t pk[4];
#pragma unroll
        for (int jj = 0; jj < 2; jj++) {
            int n = (jnp * 2 + jj) * 8 + qr;
            float f[4];
#pragma unroll
            for (int j = 0; j < 4; j++) {
                int kp  = ks * 8 + qc + (j >> 1) * 4;      // kpA, kpA, kpB, kpB
                int c96 = 2 * kp + (j & 1);
                int sidx = c96 >> 5, ci = c96 & 31;
                int base = (ci * 64 + n) * 27 + kh * 3 + kw;
                float v;
                if (sidx == 0)      v = w[base] + w[base + 9] + w[base + 18];
                else if (sidx == 1) v = -w[base];
                else                v = -w[base + 18];
                f[j] = v;
            }
            pk[jj * 2]     = pack_h2(f[0], f[1]);
            pk[jj * 2 + 1] = pack_h2(f[2], f[3]);
        }
        g_WB4[i] = make_uint4(pk[0], pk[1], pk[2], pk[3]);
    }
}

// ================= HMMA GEMM (2-way k-split, software pipelined) + fused epilogue =================
__device__ __forceinline__ void mma16816(float* d,
                                         uint32_t a0, uint32_t a1, uint32_t a2, uint32_t a3,
                                         uint32_t b0, uint32_t b1) {
    asm volatile(
        "mma.sync.aligned.m16n8k16.row.col.f32.f16.f16.f32 "
        "{%0,%1,%2,%3},{%4,%5,%6,%7},{%8,%9},{%0,%1,%2,%3};"
        : "+f"(d[0]), "+f"(d[1]), "+f"(d[2]), "+f"(d[3])
        : "r"(a0), "r"(a1), "r"(a2), "r"(a3), "r"(b0), "r"(b1));
}

// grid 512: cls=bid>>7 (heavy first), b=(bid>>4)&7, mt=bid&15. Block 64m x 64n.
// 8 warps: grp=w>>2 splits ksteps; warp handles m rows [mt*64 + (w&3)*16, +16).
__global__ void __launch_bounds__(256, 3)
mma_fused(const float* __restrict__ conv_bias,
          const float* __restrict__ bias,
          float* __restrict__ out) {
    __shared__ float scb[COUT];
    __shared__ float red[4][32][36];     // padded: kills 128B-stride bank conflicts

    const int tid  = threadIdx.x;
    const int w    = tid >> 5;
    const int lane = tid & 31;
    const int wm   = w & 3;
    const int grp  = w >> 2;
    if (tid < COUT) scb[tid] = conv_bias[tid] + bias[tid];

    const int bid = blockIdx.x;
    const int cls = bid >> 7;
    const int b   = (bid >> 4) & 7;
    const int mt  = bid & 15;
    const int mw  = mt * 64 + wm * 16;
    const int qr = lane >> 2;
    const int qc = lane & 3;

    float acc[8][4];
#pragma unroll
    for (int j = 0; j < 8; j++)
#pragma unroll
        for (int t = 0; t < 4; t++) acc[j][t] = 0.f;

    const int halfT = c_np[cls] * 3;
    const int sb = grp * halfT;
    const int se = sb + halfT;

    // pointer helpers
    const size_t a_lane = (size_t)(mw + qr) * 4 + qc;

    // prologue: load iter sb
    int pli0 = sb / 6, ks0 = sb - pli0 * 6;
    const uint2* Ap = g_XA2 + (((size_t)b * 6 + ks0) * 1072 + c_dlt[cls][pli0]) * 4 + a_lane;
    const uint4* Bp = g_WB4 + ((size_t)c_pl[cls][pli0] * 6 + ks0) * 128 + lane;
    uint2 av0 = Ap[0];
    uint2 av1 = Ap[32];
    uint4 bb0 = Bp[0], bb1 = Bp[32], bb2 = Bp[64], bb3 = Bp[96];

    for (int s = sb; s < se; s++) {
        uint2 nv0, nv1;
        uint4 nb0, nb1, nb2, nb3;
        if (s + 1 < se) {
            const int sn = s + 1;
            const int pli = sn / 6;
            const int ks  = sn - pli * 6;
            Ap = g_XA2 + (((size_t)b * 6 + ks) * 1072 + c_dlt[cls][pli]) * 4 + a_lane;
            Bp = g_WB4 + ((size_t)c_pl[cls][pli] * 6 + ks) * 128 + lane;
            nv0 = Ap[0];
            nv1 = Ap[32];
            nb0 = Bp[0]; nb1 = Bp[32]; nb2 = Bp[64]; nb3 = Bp[96];
        }
        mma16816(acc[0], av0.x, av1.x, av0.y, av1.y, bb0.x, bb0.y);
        mma16816(acc[1], av0.x, av1.x, av0.y, av1.y, bb0.z, bb0.w);
        mma16816(acc[2], av0.x, av1.x, av0.y, av1.y, bb1.x, bb1.y);
        mma16816(acc[3], av0.x, av1.x, av0.y, av1.y, bb1.z, bb1.w);
        mma16816(acc[4], av0.x, av1.x, av0.y, av1.y, bb2.x, bb2.y);
        mma16816(acc[5], av0.x, av1.x, av0.y, av1.y, bb2.z, bb2.w);
        mma16816(acc[6], av0.x, av1.x, av0.y, av1.y, bb3.x, bb3.y);
        mma16816(acc[7], av0.x, av1.x, av0.y, av1.y, bb3.z, bb3.w);
        av0 = nv0; av1 = nv1;
        bb0 = nb0; bb1 = nb1; bb2 = nb2; bb3 = nb3;
    }

    // ---- cross-group reduction ----
    if (grp == 1) {
#pragma unroll
        for (int jn = 0; jn < 8; jn += 2) {
            *(float4*)&red[wm][lane][jn * 4]     = *(float4*)&acc[jn][0];
            *(float4*)&red[wm][lane][jn * 4 + 4] = *(float4*)&acc[jn + 1][0];
        }
    }
    __syncthreads();
    if (grp == 1) return;

#pragma unroll
    for (int jn = 0; jn < 8; jn++) {
#pragma unroll
        for (int t = 0; t < 4; t++) acc[jn][t] += red[wm][lane][jn * 4 + t];
    }

    // ---- fused epilogue: mean-scale + biases + softmax + 2*tanh ----
    const float inv_d = 1.0f / 31.0f;
    float mx0 = -INFINITY, mx1 = -INFINITY;
#pragma unroll
    for (int jn = 0; jn < 8; jn++) {
#pragma unroll
        for (int t = 0; t < 2; t++) {
            float c = scb[jn * 8 + 2 * qc + t];
            acc[jn][t]     = acc[jn][t]     * inv_d + c;
            acc[jn][2 + t] = acc[jn][2 + t] * inv_d + c;
            mx0 = fmaxf(mx0, acc[jn][t]);
            mx1 = fmaxf(mx1, acc[jn][2 + t]);
        }
    }
    mx0 = fmaxf(mx0, __shfl_xor_sync(0xffffffffu, mx0, 1));
    mx0 = fmaxf(mx0, __shfl_xor_sync(0xffffffffu, mx0, 2));
    mx1 = fmaxf(mx1, __shfl_xor_sync(0xffffffffu, mx1, 1));
    mx1 = fmaxf(mx1, __shfl_xor_sync(0xffffffffu, mx1, 2));

    float s0 = 0.f, s1 = 0.f;
#pragma unroll
    for (int jn = 0; jn < 8; jn++) {
#pragma unroll
        for (int t = 0; t < 2; t++) {
            acc[jn][t]     = __expf(acc[jn][t] - mx0);
            acc[jn][2 + t] = __expf(acc[jn][2 + t] - mx1);
            s0 += acc[jn][t];
            s1 += acc[jn][2 + t];
        }
    }
    s0 += __shfl_xor_sync(0xffffffffu, s0, 1);
    s0 += __shfl_xor_sync(0xffffffffu, s0, 2);
    s1 += __shfl_xor_sync(0xffffffffu, s1, 1);
    s1 += __shfl_xor_sync(0xffffffffu, s1, 2);
    const float rs0 = 1.0f / s0;
    const float rs1 = 1.0f / s1;

    const int oh = c_oh[cls], ow = c_ow[cls];
    const int m0 = mw + qr;
    const int hq = m0 >> 5;
    const int wq0 = m0 & 31;
    const int ho = 2 * hq + oh;
    const int wo0 = 2 * wq0 + ow;
    const int wo1 = 2 * (wq0 + 8) + ow;
    float* obase = out + (size_t)b * COUT * (HOUT * HOUT) + (size_t)ho * HOUT;

    if (ho < HOUT) {
        const bool v0 = (wo0 < HOUT);
        const bool v1 = (wo1 < HOUT);
#pragma unroll
        for (int jn = 0; jn < 8; jn++) {
#pragma unroll
            for (int t = 0; t < 2; t++) {
                int ch = jn * 8 + 2 * qc + t;
                float* op = obase + (size_t)ch * (HOUT * HOUT);
                if (v0) {
                    float s = acc[jn][t] * rs0;
                    op[wo0] = __fdividef(4.0f, 1.0f + __expf(-2.0f * s)) - 2.0f;  // 2*tanh
                }
                if (v1) {
                    float s = acc[jn][2 + t] * rs1;
                    op[wo1] = __fdividef(4.0f, 1.0f + __expf(-2.0f * s)) - 2.0f;
                }
            }
        }
    }
}

extern "C" void kernel_launch(void* const* d_in, const int* in_sizes, int n_in,
                              void* d_out, int out_size) {
    (void)in_sizes; (void)n_in; (void)out_size;
    const float* x         = (const float*)d_in[0];
    const float* w         = (const float*)d_in[1];
    const float* conv_bias = (const float*)d_in[2];
    const float* bias      = (const float*)d_in[3];
    float* out             = (float*)d_out;

    // 512 prep blocks + ceil(9*6*4*32 / 128)=54 wc blocks
    prep_kernel<<<566, 128>>>(x, w);
    mma_fused<<<512, 256>>>(conv_bias, bias, out);
}

// round 13
// speedup vs baseline: 1.4291x; 1.1098x over previous
#include <cuda_runtime.h>
#include <cuda_fp16.h>
#include <math.h>
#include <cstdint>

#define NB 8
#define COUT 64
#define HOUT 63

// ---- scratch (device globals, zero-initialized; no cudaMalloc) ----
// XA2: [b][ks 6][m 1072][qc 4] -> uint2 = (hA, hB) fp16x2; kpA=ks*8+qc, kpB=kpA+4
__device__ __align__(16) uint2 g_XA2[NB * 6 * 1072 * 4];
// WB4: [pl 9][ks 6][jnp 4][lane 32] -> uint4 = (b0_e, b1_e, b0_o, b1_o) for jn=2*jnp{,+1}
__device__ __align__(16) uint4 g_WB4[9 * 6 * 4 * 32];

// classes (heavy first): 0=oo(4 planes) 1=oe(2) 2=eo(2) 3=ee(1)
__constant__ int c_dlt[4][4] = {{33,32,1,0},{32,0,0,0},{1,0,0,0},{0,0,0,0}};
__constant__ int c_pl[4][4]  = {{0,2,6,8},{1,7,0,0},{3,5,0,0},{4,0,0,0}};  // plane id kh*3+kw
__constant__ int c_oh[4] = {1, 1, 0, 0};
__constant__ int c_ow[4] = {1, 0, 1, 0};

__device__ __forceinline__ uint32_t pack_h2(float f0, float f1) {
    __half h0 = __float2half_rn(f0);
    __half h1 = __float2half_rn(f1);
    return (uint32_t)__half_as_ushort(h0) | ((uint32_t)__half_as_ushort(h1) << 16);
}

// ================= prep (+wc) single launch =================
// blocks [0,512): prep x. blocks [512, 512+54): wc weights.
__global__ void __launch_bounds__(128)
prep_kernel(const float* __restrict__ x, const float* __restrict__ w) {
    if (blockIdx.x < 512) {
        __shared__ float sm[3][32][17];
        const int b    = blockIdx.x >> 6;
        const int mb16 = blockIdx.x & 63;       // 16-m tile
        const int tid  = threadIdx.x;
        const int ci = tid >> 2;
        const int mg = tid & 3;

        const float4* p = (const float4*)x + ((size_t)(b * 32 + ci) * 16) * 256 + mb16 * 4 + mg;
        float4 v = p[0];
        float4 s = v, d0 = v, d15 = v;
#pragma unroll
        for (int d = 1; d < 16; d++) {
            float4 u = p[d * 256];
            s.x += u.x; s.y += u.y; s.z += u.z; s.w += u.w;
            if (d == 15) d15 = u;
        }
        const int mo = mg * 4;
        sm[0][ci][mo + 0] = s.x;   sm[0][ci][mo + 1] = s.y;
        sm[0][ci][mo + 2] = s.z;   sm[0][ci][mo + 3] = s.w;
        sm[1][ci][mo + 0] = d0.x;  sm[1][ci][mo + 1] = d0.y;
        sm[1][ci][mo + 2] = d0.z;  sm[1][ci][mo + 3] = d0.w;
        sm[2][ci][mo + 0] = d15.x; sm[2][ci][mo + 1] = d15.y;
        sm[2][ci][mo + 2] = d15.z; sm[2][ci][mo + 3] = d15.w;
        __syncthreads();

#pragma unroll
        for (int it = 0; it < 3; it++) {
            int i = tid + it * 128;             // 0 .. 16*6*4-1
            int qc  = i & 3;
            int ks  = (i >> 2) % 6;
            int row = i / 24;
            int kpA = ks * 8 + qc;
            int kpB = kpA + 4;
            int spA = kpA >> 4, cA = (2 * kpA) & 31;
            int spB = kpB >> 4, cB = (2 * kpB) & 31;
            uint32_t hA = pack_h2(sm[spA][cA][row], sm[spA][cA + 1][row]);
            uint32_t hB = pack_h2(sm[spB][cB][row], sm[spB][cB + 1][row]);
            size_t idx = (((size_t)b * 6 + ks) * 1072 + mb16 * 16 + row) * 4 + qc;
            g_XA2[idx] = make_uint2(hA, hB);
        }
    } else {
        // wc -> fragment layout [pl][ks][jnp][lane], two jn per uint4
        int i = (blockIdx.x - 512) * 128 + threadIdx.x;   // 0 .. 9*6*4*32-1
        if (i >= 9 * 6 * 4 * 32) return;
        int lane = i & 31;
        int jnp  = (i >> 5) & 3;
        int ks   = (i / 128) % 6;
        int pl   = i / 768;
        int qr = lane >> 2, qc = lane & 3;
        int kh = pl / 3, kw = pl % 3;
        uint32_t pk[4];
#pragma unroll
        for (int jj = 0; jj < 2; jj++) {
            int n = (jnp * 2 + jj) * 8 + qr;
            float f[4];
#pragma unroll
            for (int j = 0; j < 4; j++) {
                int kp  = ks * 8 + qc + (j >> 1) * 4;      // kpA, kpA, kpB, kpB
                int c96 = 2 * kp + (j & 1);
                int sidx = c96 >> 5, ci = c96 & 31;
                int base = (ci * 64 + n) * 27 + kh * 3 + kw;
                float v;
                if (sidx == 0)      v = w[base] + w[base + 9] + w[base + 18];
                else if (sidx == 1) v = -w[base];
                else                v = -w[base + 18];
                f[j] = v;
            }
            pk[jj * 2]     = pack_h2(f[0], f[1]);
            pk[jj * 2 + 1] = pack_h2(f[2], f[3]);
        }
        g_WB4[i] = make_uint4(pk[0], pk[1], pk[2], pk[3]);
    }
}

// ================= HMMA GEMM (unrolled planes) + fused epilogue =================
__device__ __forceinline__ void mma16816(float* d,
                                         uint32_t a0, uint32_t a1, uint32_t a2, uint32_t a3,
                                         uint32_t b0, uint32_t b1) {
    asm volatile(
        "mma.sync.aligned.m16n8k16.row.col.f32.f16.f16.f32 "
        "{%0,%1,%2,%3},{%4,%5,%6,%7},{%8,%9},{%0,%1,%2,%3};"
        : "+f"(d[0]), "+f"(d[1]), "+f"(d[2]), "+f"(d[3])
        : "r"(a0), "r"(a1), "r"(a2), "r"(a3), "r"(b0), "r"(b1));
}

// One kh/kw plane (KSN ksteps), fully unrolled: constant pointer increments ->
// ptxas folds all addresses into LDG immediates; loads hoisted across MMAs.
template <int KSN>
__device__ __forceinline__ void run_plane(float acc[8][4],
                                          const uint2* __restrict__ Ap,
                                          const uint4* __restrict__ Bp) {
    uint2 av0 = Ap[0];
    uint2 av1 = Ap[32];
    uint4 bb0 = Bp[0], bb1 = Bp[32], bb2 = Bp[64], bb3 = Bp[96];
#pragma unroll
    for (int ks = 0; ks < KSN; ks++) {
        uint2 nv0, nv1;
        uint4 nb0, nb1, nb2, nb3;
        if (ks + 1 < KSN) {
            Ap += 1072 * 4;
            Bp += 128;
            nv0 = Ap[0];
            nv1 = Ap[32];
            nb0 = Bp[0]; nb1 = Bp[32]; nb2 = Bp[64]; nb3 = Bp[96];
        }
        mma16816(acc[0], av0.x, av1.x, av0.y, av1.y, bb0.x, bb0.y);
        mma16816(acc[1], av0.x, av1.x, av0.y, av1.y, bb0.z, bb0.w);
        mma16816(acc[2], av0.x, av1.x, av0.y, av1.y, bb1.x, bb1.y);
        mma16816(acc[3], av0.x, av1.x, av0.y, av1.y, bb1.z, bb1.w);
        mma16816(acc[4], av0.x, av1.x, av0.y, av1.y, bb2.x, bb2.y);
        mma16816(acc[5], av0.x, av1.x, av0.y, av1.y, bb2.z, bb2.w);
        mma16816(acc[6], av0.x, av1.x, av0.y, av1.y, bb3.x, bb3.y);
        mma16816(acc[7], av0.x, av1.x, av0.y, av1.y, bb3.z, bb3.w);
        av0 = nv0; av1 = nv1;
        bb0 = nb0; bb1 = nb1; bb2 = nb2; bb3 = nb3;
    }
}

// grid 512: cls=bid>>7 (heavy first), b=(bid>>4)&7, mt=bid&15. Block 64m x 64n.
// 8 warps: grp=w>>2 splits k-range; warp handles m rows [mt*64 + (w&3)*16, +16).
__global__ void __launch_bounds__(256, 3)
mma_fused(const float* __restrict__ conv_bias,
          const float* __restrict__ bias,
          float* __restrict__ out) {
    __shared__ float scb[COUT];
    __shared__ float red[4][32][36];     // padded: no bank conflicts

    const int tid  = threadIdx.x;
    const int w    = tid >> 5;
    const int lane = tid & 31;
    const int wm   = w & 3;
    const int grp  = w >> 2;
    if (tid < COUT) scb[tid] = conv_bias[tid] + bias[tid];

    const int bid = blockIdx.x;
    const int cls = bid >> 7;
    const int b   = (bid >> 4) & 7;
    const int mt  = bid & 15;
    const int mw  = mt * 64 + wm * 16;
    const int qr = lane >> 2;
    const int qc = lane & 3;

    float acc[8][4];
#pragma unroll
    for (int j = 0; j < 8; j++)
#pragma unroll
        for (int t = 0; t < 4; t++) acc[j][t] = 0.f;

    const int a_lane = (mw + qr) * 4 + qc;
    const int b6     = b * 6;

    if (cls == 0) {
        const int p0 = grp * 2, p1 = p0 + 1;
        run_plane<6>(acc,
                     g_XA2 + ((size_t)b6 * 1072 + c_dlt[0][p0]) * 4 + a_lane,
                     g_WB4 + (size_t)c_pl[0][p0] * 768 + lane);
        run_plane<6>(acc,
                     g_XA2 + ((size_t)b6 * 1072 + c_dlt[0][p1]) * 4 + a_lane,
                     g_WB4 + (size_t)c_pl[0][p1] * 768 + lane);
    } else if (cls == 3) {
        const int ks0 = grp * 3;
        run_plane<3>(acc,
                     g_XA2 + (((size_t)b6 + ks0) * 1072 + c_dlt[3][0]) * 4 + a_lane,
                     g_WB4 + ((size_t)c_pl[3][0] * 6 + ks0) * 128 + lane);
    } else {
        run_plane<6>(acc,
                     g_XA2 + ((size_t)b6 * 1072 + c_dlt[cls][grp]) * 4 + a_lane,
                     g_WB4 + (size_t)c_pl[cls][grp] * 768 + lane);
    }

    // ---- cross-group reduction ----
    if (grp == 1) {
#pragma unroll
        for (int jn = 0; jn < 8; jn += 2) {
            *(float4*)&red[wm][lane][jn * 4]     = *(float4*)&acc[jn][0];
            *(float4*)&red[wm][lane][jn * 4 + 4] = *(float4*)&acc[jn + 1][0];
        }
    }
    __syncthreads();
    if (grp == 1) return;

#pragma unroll
    for (int jn = 0; jn < 8; jn++) {
#pragma unroll
        for (int t = 0; t < 4; t++) acc[jn][t] += red[wm][lane][jn * 4 + t];
    }

    // ---- fused epilogue: mean-scale + biases + softmax + 2*tanh ----
    const float inv_d = 1.0f / 31.0f;
    float mx0 = -INFINITY, mx1 = -INFINITY;
#pragma unroll
    for (int jn = 0; jn < 8; jn++) {
#pragma unroll
        for (int t = 0; t < 2; t++) {
            float c = scb[jn * 8 + 2 * qc + t];
            acc[jn][t]     = acc[jn][t]     * inv_d + c;
            acc[jn][2 + t] = acc[jn][2 + t] * inv_d + c;
            mx0 = fmaxf(mx0, acc[jn][t]);
            mx1 = fmaxf(mx1, acc[jn][2 + t]);
        }
    }
    mx0 = fmaxf(mx0, __shfl_xor_sync(0xffffffffu, mx0, 1));
    mx0 = fmaxf(mx0, __shfl_xor_sync(0xffffffffu, mx0, 2));
    mx1 = fmaxf(mx1, __shfl_xor_sync(0xffffffffu, mx1, 1));
    mx1 = fmaxf(mx1, __shfl_xor_sync(0xffffffffu, mx1, 2));

    float s0 = 0.f, s1 = 0.f;
#pragma unroll
    for (int jn = 0; jn < 8; jn++) {
#pragma unroll
        for (int t = 0; t < 2; t++) {
            acc[jn][t]     = __expf(acc[jn][t] - mx0);
            acc[jn][2 + t] = __expf(acc[jn][2 + t] - mx1);
            s0 += acc[jn][t];
            s1 += acc[jn][2 + t];
        }
    }
    s0 += __shfl_xor_sync(0xffffffffu, s0, 1);
    s0 += __shfl_xor_sync(0xffffffffu, s0, 2);
    s1 += __shfl_xor_sync(0xffffffffu, s1, 1);
    s1 += __shfl_xor_sync(0xffffffffu, s1, 2);
    const float rs0 = 1.0f / s0;
    const float rs1 = 1.0f / s1;

    const int oh = c_oh[cls], ow = c_ow[cls];
    const int m0 = mw + qr;
    const int hq = m0 >> 5;
    const int wq0 = m0 & 31;
    const int ho = 2 * hq + oh;
    const int wo0 = 2 * wq0 + ow;
    const int wo1 = 2 * (wq0 + 8) + ow;
    float* obase = out + (size_t)b * COUT * (HOUT * HOUT) + (size_t)ho * HOUT;

    if (ho < HOUT) {
        const bool v0 = (wo0 < HOUT);
        const bool v1 = (wo1 < HOUT);
#pragma unroll
        for (int jn = 0; jn < 8; jn++) {
#pragma unroll
            for (int t = 0; t < 2; t++) {
                int ch = jn * 8 + 2 * qc + t;
                float* op = obase + (size_t)ch * (HOUT * HOUT);
                if (v0) {
                    float s = acc[jn][t] * rs0;
                    op[wo0] = __fdividef(4.0f, 1.0f + __expf(-2.0f * s)) - 2.0f;  // 2*tanh
                }
                if (v1) {
                    float s = acc[jn][2 + t] * rs1;
                    op[wo1] = __fdividef(4.0f, 1.0f + __expf(-2.0f * s)) - 2.0f;
                }
            }
        }
    }
}

extern "C" void kernel_launch(void* const* d_in, const int* in_sizes, int n_in,
                              void* d_out, int out_size) {
    (void)in_sizes; (void)n_in; (void)out_size;
    const float* x         = (const float*)d_in[0];
    const float* w         = (const float*)d_in[1];
    const float* conv_bias = (const float*)d_in[2];
    const float* bias      = (const float*)d_in[3];
    float* out             = (float*)d_out;

    // 512 prep blocks + ceil(9*6*4*32 / 128)=54 wc blocks
    prep_kernel<<<566, 128>>>(x, w);
    mma_fused<<<512, 256>>>(conv_bias, bias, out);
}

// round 14
// speedup vs baseline: 1.5161x; 1.0609x over previous
#include <cuda_runtime.h>
#include <cuda_fp16.h>
#include <math.h>
#include <cstdint>

#define NB 8
#define COUT 64
#define HOUT 63

// ---- scratch (device globals, zero-initialized; no cudaMalloc) ----
// XA2: [b][ks 6][m 1072][qc 4] -> uint2 = (hA, hB) fp16x2; kpA=ks*8+qc, kpB=kpA+4
__device__ __align__(16) uint2 g_XA2[NB * 6 * 1072 * 4];
// WB4: [pl 9][ks 6][jnp 4][lane 32] -> uint4 = (b0_e, b1_e, b0_o, b1_o) for jn=2*jnp{,+1}
__device__ __align__(16) uint4 g_WB4[9 * 6 * 4 * 32];

// classes: 0=oo(4 planes) 1=oe(2) 2=eo(2) 3=ee(1); plane id kh*3+kw
__constant__ int c_dlt[4][4] = {{33,32,1,0},{32,0,0,0},{1,0,0,0},{0,0,0,0}};
__constant__ int c_pl[4][4]  = {{0,2,6,8},{1,7,0,0},{3,5,0,0},{4,0,0,0}};
__constant__ int c_oh[4] = {1, 1, 0, 0};
__constant__ int c_ow[4] = {1, 0, 1, 0};

__device__ __forceinline__ uint32_t pack_h2(float f0, float f1) {
    __half h0 = __float2half_rn(f0);
    __half h1 = __float2half_rn(f1);
    return (uint32_t)__half_as_ushort(h0) | ((uint32_t)__half_as_ushort(h1) << 16);
}

// ================= prep (+wc) single launch =================
// blocks [0,512): prep x. blocks [512, 512+54): wc weights.
__global__ void __launch_bounds__(128)
prep_kernel(const float* __restrict__ x, const float* __restrict__ w) {
    if (blockIdx.x < 512) {
        __shared__ float sm[3][32][17];
        const int b    = blockIdx.x >> 6;
        const int mb16 = blockIdx.x & 63;       // 16-m tile
        const int tid  = threadIdx.x;
        const int ci = tid >> 2;
        const int mg = tid & 3;

        const float4* p = (const float4*)x + ((size_t)(b * 32 + ci) * 16) * 256 + mb16 * 4 + mg;
        float4 v = p[0];
        float4 s = v, d0 = v, d15 = v;
#pragma unroll
        for (int d = 1; d < 16; d++) {
            float4 u = p[d * 256];
            s.x += u.x; s.y += u.y; s.z += u.z; s.w += u.w;
            if (d == 15) d15 = u;
        }
        const int mo = mg * 4;
        sm[0][ci][mo + 0] = s.x;   sm[0][ci][mo + 1] = s.y;
        sm[0][ci][mo + 2] = s.z;   sm[0][ci][mo + 3] = s.w;
        sm[1][ci][mo + 0] = d0.x;  sm[1][ci][mo + 1] = d0.y;
        sm[1][ci][mo + 2] = d0.z;  sm[1][ci][mo + 3] = d0.w;
        sm[2][ci][mo + 0] = d15.x; sm[2][ci][mo + 1] = d15.y;
        sm[2][ci][mo + 2] = d15.z; sm[2][ci][mo + 3] = d15.w;
        __syncthreads();

#pragma unroll
        for (int it = 0; it < 3; it++) {
            int i = tid + it * 128;             // 0 .. 16*6*4-1
            int qc  = i & 3;
            int ks  = (i >> 2) % 6;
            int row = i / 24;
            int kpA = ks * 8 + qc;
            int kpB = kpA + 4;
            int spA = kpA >> 4, cA = (2 * kpA) & 31;
            int spB = kpB >> 4, cB = (2 * kpB) & 31;
            uint32_t hA = pack_h2(sm[spA][cA][row], sm[spA][cA + 1][row]);
            uint32_t hB = pack_h2(sm[spB][cB][row], sm[spB][cB + 1][row]);
            size_t idx = (((size_t)b * 6 + ks) * 1072 + mb16 * 16 + row) * 4 + qc;
            g_XA2[idx] = make_uint2(hA, hB);
        }
    } else {
        // wc -> fragment layout [pl][ks][jnp][lane], two jn per uint4
        int i = (blockIdx.x - 512) * 128 + threadIdx.x;   // 0 .. 9*6*4*32-1
        if (i >= 9 * 6 * 4 * 32) return;
        int lane = i & 31;
        int jnp  = (i >> 5) & 3;
        int ks   = (i / 128) % 6;
        int pl   = i / 768;
        int qr = lane >> 2, qc = lane & 3;
        int kh = pl / 3, kw = pl % 3;
        uint32_t pk[4];
#pragma unroll
        for (int jj = 0; jj < 2; jj++) {
            int n = (jnp * 2 + jj) * 8 + qr;
            float f[4];
#pragma unroll
            for (int j = 0; j < 4; j++) {
                int kp  = ks * 8 + qc + (j >> 1) * 4;      // kpA, kpA, kpB, kpB
                int c96 = 2 * kp + (j & 1);
                int sidx = c96 >> 5, ci = c96 & 31;
                int base = (ci * 64 + n) * 27 + kh * 3 + kw;
                float v;
                if (sidx == 0)      v = w[base] + w[base + 9] + w[base + 18];
                else if (sidx == 1) v = -w[base];
                else                v = -w[base + 18];
                f[j] = v;
            }
            pk[jj * 2]     = pack_h2(f[0], f[1]);
            pk[jj * 2 + 1] = pack_h2(f[2], f[3]);
        }
        g_WB4[i] = make_uint4(pk[0], pk[1], pk[2], pk[3]);
    }
}

// ================= HMMA GEMM (balanced single wave) + fused epilogue =================
__device__ __forceinline__ void mma16816(float* d,
                                         uint32_t a0, uint32_t a1, uint32_t a2, uint32_t a3,
                                         uint32_t b0, uint32_t b1) {
    asm volatile(
        "mma.sync.aligned.m16n8k16.row.col.f32.f16.f16.f32 "
        "{%0,%1,%2,%3},{%4,%5,%6,%7},{%8,%9},{%0,%1,%2,%3};"
        : "+f"(d[0]), "+f"(d[1]), "+f"(d[2]), "+f"(d[3])
        : "r"(a0), "r"(a1), "r"(a2), "r"(a3), "r"(b0), "r"(b1));
}

// One kh/kw plane (6 ksteps), fully unrolled with 1-deep register pipeline.
__device__ __forceinline__ void run_plane6(float acc[8][4],
                                           const uint2* __restrict__ Ap,
                                           const uint4* __restrict__ Bp) {
    uint2 av0 = Ap[0];
    uint2 av1 = Ap[32];
    uint4 bb0 = Bp[0], bb1 = Bp[32], bb2 = Bp[64], bb3 = Bp[96];
#pragma unroll
    for (int ks = 0; ks < 6; ks++) {
        uint2 nv0, nv1;
        uint4 nb0, nb1, nb2, nb3;
        if (ks + 1 < 6) {
            Ap += 1072 * 4;
            Bp += 128;
            nv0 = Ap[0];
            nv1 = Ap[32];
            nb0 = Bp[0]; nb1 = Bp[32]; nb2 = Bp[64]; nb3 = Bp[96];
        }
        mma16816(acc[0], av0.x, av1.x, av0.y, av1.y, bb0.x, bb0.y);
        mma16816(acc[1], av0.x, av1.x, av0.y, av1.y, bb0.z, bb0.w);
        mma16816(acc[2], av0.x, av1.x, av0.y, av1.y, bb1.x, bb1.y);
        mma16816(acc[3], av0.x, av1.x, av0.y, av1.y, bb1.z, bb1.w);
        mma16816(acc[4], av0.x, av1.x, av0.y, av1.y, bb2.x, bb2.y);
        mma16816(acc[5], av0.x, av1.x, av0.y, av1.y, bb2.z, bb2.w);
        mma16816(acc[6], av0.x, av1.x, av0.y, av1.y, bb3.x, bb3.y);
        mma16816(acc[7], av0.x, av1.x, av0.y, av1.y, bb3.z, bb3.w);
        av0 = nv0; av1 = nv1;
        bb0 = nb0; bb1 = nb1; bb2 = nb2; bb3 = nb3;
    }
}

// grid 576, every block = 6 k-iters/warp (single balanced wave at 4 blocks/SM):
//   [0,256):   cls0, 32m tiles, 2 m-warps x 4 k-groups (1 plane each)
//   [256,384): cls1, 64m tiles, 4 m-warps x 2 k-groups
//   [384,512): cls2, 64m tiles, 4 m-warps x 2 k-groups
//   [512,576): cls3, 128m tiles, 8 m-warps x 1 k-group
__global__ void __launch_bounds__(256, 4)
mma_fused(const float* __restrict__ conv_bias,
          const float* __restrict__ bias,
          float* __restrict__ out) {
    __shared__ float scb[COUT];
    __shared__ float red[6][32][36];     // padded reduction buffer (max 6 parked warps)

    const int tid  = threadIdx.x;
    const int w    = tid >> 5;
    const int lane = tid & 31;
    if (tid < COUT) scb[tid] = conv_bias[tid] + bias[tid];

    const int bid = blockIdx.x;
    int cls, b, mbase, lgNMW;
    if (bid < 256)      { cls = 0; b = bid >> 5;         mbase = (bid & 31) * 32;          lgNMW = 1; }
    else if (bid < 384) { cls = 1; b = (bid - 256) >> 4; mbase = ((bid - 256) & 15) * 64;  lgNMW = 2; }
    else if (bid < 512) { cls = 2; b = (bid - 384) >> 4; mbase = ((bid - 384) & 15) * 64;  lgNMW = 2; }
    else                { cls = 3; b = (bid - 512) >> 3; mbase = ((bid - 512) & 7) * 128;  lgNMW = 3; }
    const int NMW = 1 << lgNMW;
    const int NKG = 8 >> lgNMW;
    const int wm  = w & (NMW - 1);
    const int grp = w >> lgNMW;
    const int mw  = mbase + wm * 16;
    const int qr = lane >> 2;
    const int qc = lane & 3;

    float acc[8][4];
#pragma unroll
    for (int j = 0; j < 8; j++)
#pragma unroll
        for (int t = 0; t < 4; t++) acc[j][t] = 0.f;

    const int a_lane = (mw + qr) * 4 + qc;

    // every warp: exactly one plane of 6 ksteps
    run_plane6(acc,
               g_XA2 + ((size_t)(b * 6) * 1072 + c_dlt[cls][grp]) * 4 + a_lane,
               g_WB4 + (size_t)c_pl[cls][grp] * 768 + lane);

    // ---- cross-group reduction ----
    if (grp > 0) {
        const int ri = (grp - 1) * NMW + wm;
#pragma unroll
        for (int jn = 0; jn < 8; jn += 2) {
            *(float4*)&red[ri][lane][jn * 4]     = *(float4*)&acc[jn][0];
            *(float4*)&red[ri][lane][jn * 4 + 4] = *(float4*)&acc[jn + 1][0];
        }
    }
    __syncthreads();
    if (grp > 0) return;

    for (int g = 1; g < NKG; g++) {
        const int ri = (g - 1) * NMW + wm;
#pragma unroll
        for (int jn = 0; jn < 8; jn++) {
#pragma unroll
            for (int t = 0; t < 4; t++) acc[jn][t] += red[ri][lane][jn * 4 + t];
        }
    }

    // ---- fused epilogue: mean-scale + biases + softmax + 2*tanh ----
    const float inv_d = 1.0f / 31.0f;
    float mx0 = -INFINITY, mx1 = -INFINITY;
#pragma unroll
    for (int jn = 0; jn < 8; jn++) {
#pragma unroll
        for (int t = 0; t < 2; t++) {
            float c = scb[jn * 8 + 2 * qc + t];
            acc[jn][t]     = acc[jn][t]     * inv_d + c;
            acc[jn][2 + t] = acc[jn][2 + t] * inv_d + c;
            mx0 = fmaxf(mx0, acc[jn][t]);
            mx1 = fmaxf(mx1, acc[jn][2 + t]);
        }
    }
    mx0 = fmaxf(mx0, __shfl_xor_sync(0xffffffffu, mx0, 1));
    mx0 = fmaxf(mx0, __shfl_xor_sync(0xffffffffu, mx0, 2));
    mx1 = fmaxf(mx1, __shfl_xor_sync(0xffffffffu, mx1, 1));
    mx1 = fmaxf(mx1, __shfl_xor_sync(0xffffffffu, mx1, 2));

    float s0 = 0.f, s1 = 0.f;
#pragma unroll
    for (int jn = 0; jn < 8; jn++) {
#pragma unroll
        for (int t = 0; t < 2; t++) {
            acc[jn][t]     = __expf(acc[jn][t] - mx0);
            acc[jn][2 + t] = __expf(acc[jn][2 + t] - mx1);
            s0 += acc[jn][t];
            s1 += acc[jn][2 + t];
        }
    }
    s0 += __shfl_xor_sync(0xffffffffu, s0, 1);
    s0 += __shfl_xor_sync(0xffffffffu, s0, 2);
    s1 += __shfl_xor_sync(0xffffffffu, s1, 1);
    s1 += __shfl_xor_sync(0xffffffffu, s1, 2);
    const float rs0 = 1.0f / s0;
    const float rs1 = 1.0f / s1;

    const int oh = c_oh[cls], ow = c_ow[cls];
    const int m0 = mw + qr;
    const int hq = m0 >> 5;
    const int wq0 = m0 & 31;
    const int ho = 2 * hq + oh;
    const int wo0 = 2 * wq0 + ow;
    const int wo1 = 2 * (wq0 + 8) + ow;
    float* obase = out + (size_t)b * COUT * (HOUT * HOUT) + (size_t)ho * HOUT;

    if (ho < HOUT) {
        const bool v0 = (wo0 < HOUT);
        const bool v1 = (wo1 < HOUT);
#pragma unroll
        for (int jn = 0; jn < 8; jn++) {
#pragma unroll
            for (int t = 0; t < 2; t++) {
                int ch = jn * 8 + 2 * qc + t;
                float* op = obase + (size_t)ch * (HOUT * HOUT);
                if (v0) {
                    float s = acc[jn][t] * rs0;
                    op[wo0] = __fdividef(4.0f, 1.0f + __expf(-2.0f * s)) - 2.0f;  // 2*tanh
                }
                if (v1) {
                    float s = acc[jn][2 + t] * rs1;
                    op[wo1] = __fdividef(4.0f, 1.0f + __expf(-2.0f * s)) - 2.0f;
                }
            }
        }
    }
}

extern "C" void kernel_launch(void* const* d_in, const int* in_sizes, int n_in,
                              void* d_out, int out_size) {
    (void)in_sizes; (void)n_in; (void)out_size;
    const float* x         = (const float*)d_in[0];
    const float* w         = (const float*)d_in[1];
    const float* conv_bias = (const float*)d_in[2];
    const float* bias      = (const float*)d_in[3];
    float* out             = (float*)d_out;

    // 512 prep blocks + ceil(9*6*4*32 / 128)=54 wc blocks
    prep_kernel<<<566, 128>>>(x, w);
    mma_fused<<<576, 256>>>(conv_bias, bias, out);
}